// round 17
// baseline (speedup 1.0000x reference)
#include <cuda_runtime.h>
#include <cuda_fp16.h>
#include <cstdint>
#include <math.h>

__device__ float g_c1[48*256*900];
__device__ float g_xe[48*256*900];
__device__ float g_xd[48*256*900];
__device__ float g_q [48*900*768];
__device__ float g_k [48*900*512];
__device__ float g_z [900*8*48*48];
__device__ float g_csum[8*48*48];
__device__ float g_ao[48*900*256];
__device__ float g_t1[48*900*256];
__device__ float g_t2[48*900*256];
__device__ float g_t3[48*900*256];
__device__ float g_y [48*900];
__device__ __half g_a[99532800u];
__device__ __half g_b[2359296u];
__device__ __half g_xeh[11059200u];
__device__ __half g_xdh[11059200u];
__device__ __half g_t1h[11059200u];
__device__ __half g_t2h[11059200u];
__device__ __half g_t3h[11059200u];

__global__ void mma_gemm_k(const __half* A, const __half* B,
                           const float* bias, float* C, __half* H,
                           int M, int N, int K, int mode);
__global__ void w_h_k(const float* w, __half* out, int N, int K, int Kp);
__global__ void im2col1_h(const float* X, __half* out);
__global__ void im2col2_h(const __half* in, __half* out);
__global__ void attn_scores_k(const float* Q, const float* Kb, const float* RW, float* Z,
                              int qs, int ks);
__global__ void attn_scores_masked_k(const float* Q, const float* Kb, const float* RW,
                                     const float* L1w, const float* L1b,
                                     const float* L2w, const float* L2b, float* Z,
                                     int qs, int ks);
__global__ void col_softmax_k(float* Z, float* csum);
__global__ void attn_out_k(const float* Z, const float* csum, const float* V, float* O, int vs);
__global__ void add_ln_k(const float* A, const float* B, float* O, __half* H);
__global__ void outproj_k(const float* H, const float* w, const float* b, float* y);
__global__ void final_softmax_k(const float* y, float* out);

extern "C" void kernel_launch(void* const* d_in, const int* in_sizes, int n_in,
                              void* d_out, int out_size)
{
    const float* X_en = (const float*)d_in[0];
    const float* X_de = (const float*)d_in[1];
    const float* c1w = (const float*)d_in[2];
    const float* c1b = (const float*)d_in[3];
    const float* c2w = (const float*)d_in[4];
    const float* c2b = (const float*)d_in[5];
    const float* enc_wq = (const float*)d_in[6];
    const float* enc_wk = (const float*)d_in[7];
    const float* enc_wv = (const float*)d_in[8];
    const float* enc_rel = (const float*)d_in[9];
    const float* e_w1 = (const float*)d_in[10];
    const float* e_b1 = (const float*)d_in[11];
    const float* e_w2 = (const float*)d_in[12];
    const float* e_b2 = (const float*)d_in[13];
    const float* m_wq = (const float*)d_in[14];
    const float* m_wk = (const float*)d_in[15];
    const float* m_wv = (const float*)d_in[16];
    const float* m_rel = (const float*)d_in[17];
    const float* l1w = (const float*)d_in[18];
    const float* l1b = (const float*)d_in[19];
    const float* l2w = (const float*)d_in[20];
    const float* l2b = (const float*)d_in[21];
    const float* c_wq = (const float*)d_in[22];
    const float* c_wk = (const float*)d_in[23];
    const float* c_wv = (const float*)d_in[24];
    const float* c_rel = (const float*)d_in[25];
    const float* d_w1 = (const float*)d_in[26];
    const float* d_b1 = (const float*)d_in[27];
    const float* d_w2 = (const float*)d_in[28];
    const float* d_b2 = (const float*)d_in[29];
    const float* ow = (const float*)d_in[30];
    const float* ob = (const float*)d_in[31];

    float *c1, *xe, *xd, *q, *k, *z, *cs, *ao, *t1, *t2, *t3, *yv;
    __half *ha, *hb, *xeh, *xdh, *t1h, *t2h, *t3h;
    cudaGetSymbolAddress((void**)&c1, g_c1);
    cudaGetSymbolAddress((void**)&xe, g_xe);
    cudaGetSymbolAddress((void**)&xd, g_xd);
    cudaGetSymbolAddress((void**)&q,  g_q);
    cudaGetSymbolAddress((void**)&k,  g_k);
    cudaGetSymbolAddress((void**)&z,  g_z);
    cudaGetSymbolAddress((void**)&cs, g_csum);
    cudaGetSymbolAddress((void**)&ao, g_ao);
    cudaGetSymbolAddress((void**)&t1, g_t1);
    cudaGetSymbolAddress((void**)&t2, g_t2);
    cudaGetSymbolAddress((void**)&t3, g_t3);
    cudaGetSymbolAddress((void**)&yv, g_y);
    cudaGetSymbolAddress((void**)&ha, g_a);
    cudaGetSymbolAddress((void**)&hb, g_b);
    cudaGetSymbolAddress((void**)&xeh, g_xeh);
    cudaGetSymbolAddress((void**)&xdh, g_xdh);
    cudaGetSymbolAddress((void**)&t1h, g_t1h);
    cudaGetSymbolAddress((void**)&t2h, g_t2h);
    cudaGetSymbolAddress((void**)&t3h, g_t3h);
    __half* c1h = (__half*)c1;

    cudaFuncSetAttribute(mma_gemm_k, cudaFuncAttributeMaxDynamicSharedMemorySize, 110592);

    const int M = 43200;
    const unsigned smem_bytes = 110592;
    dim3 agrid(900, 8);
    dim3 g256(2, 338);
    dim3 g512(4, 338);
    dim3 g768(6, 338);
    dim3 g1024(8, 338);
    const float* nobias = 0;
    __half* noh = 0;
    float* nof = 0;

    // ---- conv stacks ----
    w_h_k<<<320, 256>>>(c1w, hb, 256, 288, 320);
    im2col1_h<<<5400, 256>>>(X_en, ha);
    mma_gemm_k<<<g256, 256, smem_bytes>>>(ha, hb, c1b, nof, c1h, M, 256, 320, 6);
    w_h_k<<<2304, 256>>>(c2w, hb, 256, 2304, 2304);
    im2col2_h<<<43200, 256>>>(c1h, ha);
    mma_gemm_k<<<g256, 256, smem_bytes>>>(ha, hb, c2b, xe, xeh, M, 256, 2304, 5);

    w_h_k<<<320, 256>>>(c1w, hb, 256, 288, 320);
    im2col1_h<<<5400, 256>>>(X_de, ha);
    mma_gemm_k<<<g256, 256, smem_bytes>>>(ha, hb, c1b, nof, c1h, M, 256, 320, 6);
    w_h_k<<<2304, 256>>>(c2w, hb, 256, 2304, 2304);
    im2col2_h<<<43200, 256>>>(c1h, ha);
    mma_gemm_k<<<g256, 256, smem_bytes>>>(ha, hb, c2b, xd, xdh, M, 256, 2304, 5);

    // ---- encoder ----
    w_h_k<<<256, 256>>>(enc_wq, hb, 256, 256, 256);
    w_h_k<<<256, 256>>>(enc_wk, hb + 65536, 256, 256, 256);
    w_h_k<<<256, 256>>>(enc_wv, hb + 131072, 256, 256, 256);
    mma_gemm_k<<<g768, 256, smem_bytes>>>(xeh, hb, nobias, q, noh, M, 768, 256, 0);
    attn_scores_k<<<agrid, 256>>>(q, q + 256, enc_rel, z, 768, 768);
    col_softmax_k<<<72, 256>>>(z, cs);
    attn_out_k<<<agrid, 256>>>(z, cs, q + 512, ao, 768);
    add_ln_k<<<43200, 256>>>(xe, ao, t1, t1h);
    w_h_k<<<1024, 256>>>(e_w1, hb, 1024, 256, 256);
    mma_gemm_k<<<g1024, 256, smem_bytes>>>(t1h, hb, e_b1, nof, ha, M, 1024, 256, 3);
    w_h_k<<<1024, 256>>>(e_w2, hb, 256, 1024, 1024);
    mma_gemm_k<<<g256, 256, smem_bytes>>>(ha, hb, e_b2, ao, noh, M, 256, 1024, 0);
    add_ln_k<<<43200, 256>>>(t1, ao, t2, t2h);

    // ---- decoder masked self-attn ----
    w_h_k<<<256, 256>>>(m_wq, hb, 256, 256, 256);
    w_h_k<<<256, 256>>>(m_wk, hb + 65536, 256, 256, 256);
    w_h_k<<<256, 256>>>(m_wv, hb + 131072, 256, 256, 256);
    mma_gemm_k<<<g768, 256, smem_bytes>>>(xdh, hb, nobias, q, noh, M, 768, 256, 0);
    attn_scores_masked_k<<<agrid, 256>>>(q, q + 256, m_rel, l1w, l1b, l2w, l2b, z, 768, 768);
    col_softmax_k<<<72, 256>>>(z, cs);
    attn_out_k<<<agrid, 256>>>(z, cs, q + 512, ao, 768);
    add_ln_k<<<43200, 256>>>(xd, ao, t1, t1h);

    // ---- decoder cross-attn ----
    w_h_k<<<256, 256>>>(c_wq, hb, 256, 256, 256);
    mma_gemm_k<<<g256, 256, smem_bytes>>>(t1h, hb, nobias, q, noh, M, 256, 256, 0);
    w_h_k<<<256, 256>>>(c_wk, hb, 256, 256, 256);
    w_h_k<<<256, 256>>>(c_wv, hb + 65536, 256, 256, 256);
    mma_gemm_k<<<g512, 256, smem_bytes>>>(t2h, hb, nobias, k, noh, M, 512, 256, 0);
    attn_scores_k<<<agrid, 256>>>(q, k, c_rel, z, 256, 512);
    col_softmax_k<<<72, 256>>>(z, cs);
    attn_out_k<<<agrid, 256>>>(z, cs, k + 256, ao, 512);
    add_ln_k<<<43200, 256>>>(ao, t1, t3, t3h);
    w_h_k<<<1024, 256>>>(d_w1, hb, 1024, 256, 256);
    mma_gemm_k<<<g1024, 256, smem_bytes>>>(t3h, hb, d_b1, nof, ha, M, 1024, 256, 3);
    w_h_k<<<1024, 256>>>(d_w2, hb, 256, 1024, 1024);
    mma_gemm_k<<<g256, 256, smem_bytes>>>(ha, hb, d_b2, ao, noh, M, 256, 1024, 0);
    add_ln_k<<<43200, 256>>>(t3, ao, t1, noh);

    outproj_k<<<5400, 256>>>(t1, ow, ob, yv);
    final_softmax_k<<<4, 256>>>(yv, (float*)d_out);
}

__device__ __forceinline__ unsigned smem_u32(const void* p)
{
    unsigned a;
    asm("{ .reg .u64 t; cvta.to.shared.u64 t, %1; cvt.u32.u64 %0, t; }" : "=r"(a) : "l"(p));
    return a;
}

__device__ __forceinline__ void mma16816(float* c, const unsigned* a, unsigned b0, unsigned b1)
{
    asm volatile("mma.sync.aligned.m16n8k16.row.col.f32.f16.f16.f32 {%0,%1,%2,%3}, {%4,%5,%6,%7}, {%8,%9}, {%0,%1,%2,%3};" : "+f"(c[0]), "+f"(c[1]), "+f"(c[2]), "+f"(c[3]) : "r"(a[0]), "r"(a[1]), "r"(a[2]), "r"(a[3]), "r"(b0), "r"(b1));
}

__device__ __forceinline__ void ldmx4(unsigned* r, unsigned addr)
{
    asm volatile("ldmatrix.sync.aligned.m8n8.x4.shared.b16 {%0,%1,%2,%3}, [%4];" : "=r"(r[0]), "=r"(r[1]), "=r"(r[2]), "=r"(r[3]) : "r"(addr));
}

__device__ __forceinline__ void stage_issue(
    const __half* A, const __half* B,
    unsigned st, int m0, int n0, int M, int K, int koff, int tid)
{
    for (int j = 0; j < 8; j++) {
        int i = tid + j * 256;
        int t = i >> 10;
        int r = (i >> 3) & 127;
        int c = i & 7;
        const __half* bp;
        int row;
        if (t == 0) {
            row = m0 + r;
            if (row >= M) row = M - 1;
            bp = A;
        } else {
            row = n0 + r;
            bp = B;
        }
        const __half* g = bp + (size_t)row * K + koff + c * 8;
        unsigned s = st + t * 18432 + r * 144 + c * 16;
        asm volatile("cp.async.ca.shared.global [%0], [%1], 16;" :: "r"(s), "l"(g) : "memory");
    }
    asm volatile("cp.async.commit_group;" ::: "memory");
}

__global__ __launch_bounds__(256, 2) void mma_gemm_k(
    const __half* A, const __half* B,
    const float* bias, float* C, __half* H,
    int M, int N, int K, int mode)
{
    extern __shared__ char smem[];
    const int tid = threadIdx.x;
    const int m0 = blockIdx.y * 128;
    const int n0 = blockIdx.x * 128;
    const int warp = tid >> 5;
    const int lane = tid & 31;
    const int wm = warp & 3;
    const int wn = warp >> 2;
    const int gid = lane >> 2;
    const int tig = lane & 3;
    const unsigned sbase = smem_u32(smem);

    const int arow = wm * 32 + (lane & 15);
    const int acolb = ((lane >> 4) & 1) * 16;
    const int nrow = (lane & 7) + ((lane >> 4) & 1) * 8;
    const int bcolb = ((lane >> 3) & 1) * 16;

    float acc[2][8][4];
    for (int mf = 0; mf < 2; mf++)
        for (int nf = 0; nf < 8; nf++)
            for (int e = 0; e < 4; e++)
                acc[mf][nf][e] = 0.f;

    const int nk = K >> 6;
    stage_issue(A, B, sbase, m0, n0, M, K, 0, tid);
    stage_issue(A, B, sbase + 36864u, m0, n0, M, K, 64, tid);

    for (int kb = 0; kb < nk; kb++) {
        if (kb + 1 < nk) {
            asm volatile("cp.async.wait_group 1;" ::: "memory");
        } else {
            asm volatile("cp.async.wait_group 0;" ::: "memory");
        }
        __syncthreads();

        unsigned stg = sbase;
        {
            int sidx = kb % 3;
            if (sidx == 1) stg = sbase + 36864u;
            if (sidx == 2) stg = sbase + 73728u;
        }
        for (int ks = 0; ks < 4; ks++) {
            const int kbyte = ks * 32;
            unsigned af[2][4];
            for (int mf = 0; mf < 2; mf++) {
                const unsigned arowoff = (unsigned)(arow + mf * 16) * 144u + kbyte + acolb;
                ldmx4(af[mf], stg + arowoff);
            }
            for (int nfg = 0; nfg < 4; nfg++) {
                const unsigned browoff = (unsigned)(wn * 64 + nfg * 16 + nrow) * 144u + kbyte + bcolb;
                unsigned b4[4];
                ldmx4(b4, stg + 18432u + browoff);
                for (int sub = 0; sub < 2; sub++) {
                    const int nf = nfg * 2 + sub;
                    for (int mf = 0; mf < 2; mf++) {
                        mma16816(acc[mf][nf], af[mf], b4[sub * 2], b4[sub * 2 + 1]);
                    }
                }
            }
        }
        if (kb + 2 < nk) {
            int nidx = (kb + 2) % 3;
            unsigned nst = sbase;
            if (nidx == 1) nst = sbase + 36864u;
            if (nidx == 2) nst = sbase + 73728u;
            stage_issue(A, B, nst, m0, n0, M, K, (kb + 2) * 64, tid);
        }
    }

    for (int mf = 0; mf < 2; mf++) {
        for (int nf = 0; nf < 8; nf++) {
            const int col = n0 + wn * 64 + nf * 8 + tig * 2;
            float bv0 = 0.f;
            float bv1 = 0.f;
            if (bias) {
                bv0 = bias[col];
                bv1 = bias[col + 1];
            }
            for (int half2i = 0; half2i < 2; half2i++) {
                const int m = m0 + wm * 32 + mf * 16 + gid + half2i * 8;
                if (m < M) {
                    float v0 = acc[mf][nf][half2i * 2 + 0] + bv0;
                    float v1 = acc[mf][nf][half2i * 2 + 1] + bv1;
                    if (mode == 3) {
                        v0 = fmaxf(v0, 0.f);
                        v1 = fmaxf(v1, 0.f);
                        __half* hrow = H + (size_t)m * N + col;
                        hrow[0] = __float2half(v0);
                        hrow[1] = __float2half(v1);
                    } else if (mode == 5 || mode == 6) {
                        const int b = m / 900;
                        const int p = m - b * 900;
                        size_t off = (size_t)b * 230400 + (size_t)col * 900 + p;
                        if (mode == 5) {
                            C[off] = v0;
                            C[off + 900] = v1;
                        }
                        H[off] = __float2half(v0);
                        H[off + 900] = __float2half(v1);
                    } else {
                        float2 stv;
                        stv.x = v0;
                        stv.y = v1;
                        *(float2*)(C + (size_t)m * N + col) = stv;
                    }
                }
            }
        }
    }
}

__global__ __launch_bounds__(256) void w_h_k(const float* w, __half* out, int N, int K, int Kp)
{
    int i = blockIdx.x * 256 + threadIdx.x;
    if (i >= N * Kp) return;
    int r = i / Kp;
    int k = i - r * Kp;
    float v = 0.f;
    if (k < K) v = w[(size_t)r * K + k];
    out[i] = __float2half(v);
}

__global__ __launch_bounds__(256) void im2col1_h(const float* X, __half* out)
{
    int idx = blockIdx.x * 256 + threadIdx.x;
    int m = idx >> 5;
    int ic = idx & 31;
    int b = m / 900;
    int p = m - b * 900;
    int y = p / 30;
    int x = p - y * 30;
    const float* src = X + ((size_t)(b * 32 + ic)) * 1024;
    __half* dst = out + (size_t)m * 320 + ic * 9;
    for (int ky = 0; ky < 3; ky++) {
        for (int kx = 0; kx < 3; kx++) {
            dst[ky * 3 + kx] = __float2half(src[(y + ky) * 32 + x + kx]);
        }
    }
    out[(size_t)m * 320 + 288 + ic] = __float2half(0.f);
}

__global__ __launch_bounds__(256) void im2col2_h(const __half* in, __half* out)
{
    int m = blockIdx.x;
    int ic = threadIdx.x;
    int b = m / 900;
    int p = m - b * 900;
    int y = p / 30;
    int x = p - y * 30;
    const __half* src = in + ((size_t)(b * 256 + ic)) * 900;
    __half* dst = out + (size_t)m * 2304 + ic * 9;
    for (int ky = 0; ky < 3; ky++) {
        int iy = y + ky - 1;
        for (int kx = 0; kx < 3; kx++) {
            int ix = x + kx - 1;
            __half v = __float2half(0.f);
            if (iy >= 0 && iy < 30 && ix >= 0 && ix < 30) {
                v = src[iy * 30 + ix];
            }
            dst[ky * 3 + kx] = v;
        }
    }
}

__global__ __launch_bounds__(256) void attn_scores_k(
    const float* Q, const float* Kb, const float* RW, float* Z, int qs, int ks)
{
    const int s = blockIdx.x;
    const int h = blockIdx.y;
    const int tid = threadIdx.x;
    __shared__ float sq[48][33];
    __shared__ float sk[48][33];
    __shared__ float sw[32][49];
    __shared__ float se[48][49];
    for (int e = tid; e < 1536; e += 256) {
        int i = e >> 5;
        int d = e & 31;
        sq[i][d] = Q [(size_t)(s * 48 + i) * qs + h * 32 + d];
        sk[i][d] = Kb[(size_t)(s * 48 + i) * ks + h * 32 + d];
    }
    for (int e = tid; e < 1536; e += 256) {
        int d = e / 48;
        int j = e - d * 48;
        sw[d][j] = RW[(((size_t)s * 8 + h) * 32 + d) * 48 + j];
    }
    __syncthreads();
    const int i0 = (tid >> 4) * 3;
    const int j0 = (tid & 15) * 3;
    float sc[3][3];
    float em[3][3];
    for (int a = 0; a < 3; a++) {
        for (int b = 0; b < 3; b++) {
            sc[a][b] = 0.f;
            em[a][b] = 0.f;
        }
    }
    for (int d = 0; d < 32; d++) {
        float qv[3];
        float kv[3];
        float wv[3];
        for (int a = 0; a < 3; a++) {
            qv[a] = sq[i0 + a][d];
            kv[a] = sk[j0 + a][d];
            wv[a] = sw[d][j0 + a];
        }
        for (int a = 0; a < 3; a++) {
            for (int b = 0; b < 3; b++) {
                sc[a][b] += qv[a] * kv[b];
                em[a][b] += qv[a] * wv[b];
            }
        }
    }
    for (int a = 0; a < 3; a++)
        for (int b = 0; b < 3; b++)
            se[i0 + a][j0 + b] = em[a][b];
    __syncthreads();
    size_t base = (size_t)s * 18432 + (size_t)h * 2304;
    for (int a = 0; a < 3; a++) {
        for (int b = 0; b < 3; b++) {
            int i = i0 + a;
            int j = j0 + b;
            float zz = sc[a][b] * 0.17677669529663689f;
            if (j <= i) zz += se[i][47 - i + j];
            Z[base + i * 48 + j] = zz;
        }
    }
}

__global__ __launch_bounds__(256) void attn_scores_masked_k(
    const float* Q, const float* Kb, const float* RW,
    const float* L1w, const float* L1b,
    const float* L2w, const float* L2b, float* Z, int qs, int ks)
{
    const int s = blockIdx.x;
    const int h = blockIdx.y;
    const int tid = threadIdx.x;
    __shared__ float sq[48][33];
    __shared__ float sk[48][33];
    __shared__ float sw[32][49];
    __shared__ float se[48][49];
    __shared__ float ss[48][49];
    __shared__ float s1[48][49];
    for (int e = tid; e < 1536; e += 256) {
        int i = e >> 5;
        int d = e & 31;
        sq[i][d] = Q [(size_t)(s * 48 + i) * qs + h * 32 + d];
        sk[i][d] = Kb[(size_t)(s * 48 + i) * ks + h * 32 + d];
    }
    for (int e = tid; e < 1536; e += 256) {
        int d = e / 48;
        int j = e - d * 48;
        sw[d][j] = RW[(((size_t)s * 8 + h) * 32 + d) * 48 + j];
    }
    __syncthreads();
    const int i0 = (tid >> 4) * 3;
    const int j0 = (tid & 15) * 3;
    float sc[3][3];
    float em[3][3];
    for (int a = 0; a < 3; a++) {
        for (int b = 0; b < 3; b++) {
            sc[a][b] = 0.f;
            em[a][b] = 0.f;
        }
    }
    for (int d = 0; d < 32; d++) {
        float qv[3];
        float kv[3];
        float wv[3];
        for (int a = 0; a < 3; a++) {
            qv[a] = sq[i0 + a][d];
            kv[a] = sk[j0 + a][d];
            wv[a] = sw[d][j0 + a];
        }
        for (int a = 0; a < 3; a++) {
            for (int b = 0; b < 3; b++) {
                sc[a][b] += qv[a] * kv[b];
                em[a][b] += qv[a] * wv[b];
            }
        }
    }
    for (int a = 0; a < 3; a++) {
        for (int b = 0; b < 3; b++) {
            ss[i0 + a][j0 + b] = sc[a][b] * 0.17677669529663689f;
            se[i0 + a][j0 + b] = em[a][b];
        }
    }
    __syncthreads();
    float p2[3][3];
    for (int b = 0; b < 3; b++) {
        float bv = L1b[j0 + b];
        for (int a = 0; a < 3; a++) p2[a][b] = bv;
    }
    for (int c = 0; c < 48; c++) {
        float sv[3];
        float wl[3];
        for (int a = 0; a < 3; a++) sv[a] = ss[i0 + a][c];
        for (int b = 0; b < 3; b++) wl[b] = __ldg(&L1w[(j0 + b) * 48 + c]);
        for (int a = 0; a < 3; a++)
            for (int b = 0; b < 3; b++)
                p2[a][b] += sv[a] * wl[b];
    }
    for (int a = 0; a < 3; a++)
        for (int b = 0; b < 3; b++)
            s1[i0 + a][j0 + b] = p2[a][b];
    __syncthreads();
    float p3[3][3];
    for (int b = 0; b < 3; b++) {
        float bv = L2b[j0 + b];
        for (int a = 0; a < 3; a++) p3[a][b] = bv;
    }
    for (int c = 0; c < 48; c++) {
        float sv[3];
        float wl[3];
        for (int a = 0; a < 3; a++) sv[a] = s1[c][i0 + a];
        for (int b = 0; b < 3; b++) wl[b] = __ldg(&L2w[(j0 + b) * 48 + c]);
        for (int a = 0; a < 3; a++)
            for (int b = 0; b < 3; b++)
                p3[a][b] += sv[a] * wl[b];
    }
    size_t base = (size_t)s * 18432 + (size_t)h * 2304;
    for (int a = 0; a < 3; a++) {
        for (int b = 0; b < 3; b++) {
            int ia = i0 + a;
            int jb = j0 + b;
            float acc = p3[a][b];
            if (jb > ia) acc -= 3.402823466e+38f;
            if (jb <= ia) acc += se[ia][47 - ia + jb];
            Z[base + ia * 48 + jb] = acc;
        }
    }
}

__global__ __launch_bounds__(256) void col_softmax_k(float* Z, float* csum)
{
    int c = blockIdx.x * 256 + threadIdx.x;
    float* p = Z + c;
    float m = -3.402823466e+38f;
    for (int s = 0; s < 900; s++) m = fmaxf(m, p[(size_t)s * 18432]);
    float sum = 0.f;
    for (int s = 0; s < 900; s++) {
        float v = __expf(p[(size_t)s * 18432] - m);
        p[(size_t)s * 18432] = v;
        sum += v;
    }
    csum[c] = sum;
}

__global__ __launch_bounds__(256) void attn_out_k(
    const float* Z, const float* csum, const float* V, float* O, int vs)
{
    const int s = blockIdx.x;
    const int h = blockIdx.y;
    const int tid = threadIdx.x;
    __shared__ float sp[48][49];
    __shared__ float sv[48][33];
    size_t base = (size_t)s * 18432 + (size_t)h * 2304;
    for (int e = tid; e < 2304; e += 256) {
        int i = e / 48;
        int j = e - i * 48;
        sp[i][j] = Z[base + e] / csum[h * 2304 + e];
    }
    for (int e = tid; e < 1536; e += 256) {
        int j = e >> 5;
        int d = e & 31;
        sv[j][d] = V[(size_t)(s * 48 + j) * vs + h * 32 + d];
    }
    __syncthreads();
    const int i0 = (tid >> 4) * 3;
    const int d0 = (tid & 15) * 2;
    float acc[3][2];
    for (int a = 0; a < 3; a++) {
        acc[a][0] = 0.f;
        acc[a][1] = 0.f;
    }
    for (int j = 0; j < 48; j++) {
        float pv[3];
        float vv[2];
        for (int a = 0; a < 3; a++) pv[a] = sp[i0 + a][j];
        vv[0] = sv[j][d0];
        vv[1] = sv[j][d0 + 1];
        for (int a = 0; a < 3; a++) {
            acc[a][0] += pv[a] * vv[0];
            acc[a][1] += pv[a] * vv[1];
        }
    }
    for (int a = 0; a < 3; a++) {
        size_t off = (size_t)((s * 8 + h) * 48 + i0 + a) * 32 + d0;
        O[off] = acc[a][0];
        O[off + 1] = acc[a][1];
    }
}

__device__ __forceinline__ float block_sum256(float v, float* sbuf)
{
    for (int o = 16; o > 0; o >>= 1) v += __shfl_down_sync(0xffffffffu, v, o);
    int w = threadIdx.x >> 5;
    int l = threadIdx.x & 31;
    if (l == 0) sbuf[w] = v;
    __syncthreads();
    if (w == 0) {
        v = (l < 8) ? sbuf[l] : 0.f;
        for (int o = 4; o > 0; o >>= 1) v += __shfl_down_sync(0xffffffffu, v, o);
        if (l == 0) sbuf[0] = v;
    }
    __syncthreads();
    float r = sbuf[0];
    __syncthreads();
    return r;
}

__global__ __launch_bounds__(256) void add_ln_k(const float* A, const float* B, float* O, __half* H)
{
    __shared__ float sbuf[8];
    size_t base = (size_t)blockIdx.x * 256;
    float v = A[base + threadIdx.x] + B[base + threadIdx.x];
    float mean = block_sum256(v, sbuf) * (1.f / 256.f);
    float d = v - mean;
    float var = block_sum256(d * d, sbuf) * (1.f / 256.f);
    float r = d * rsqrtf(var + 1e-5f);
    O[base + threadIdx.x] = r;
    if (H) H[base + threadIdx.x] = __float2half(r);
}

__global__ __launch_bounds__(256) void outproj_k(const float* H, const float* w,
                                                 const float* b, float* y)
{
    int warp = (blockIdx.x * 256 + threadIdx.x) >> 5;
    int lane = threadIdx.x & 31;
    if (warp >= 43200) return;
    const float* row = H + (size_t)warp * 256;
    float s = 0.f;
    for (int k = lane; k < 256; k += 32) s += row[k] * w[k];
    for (int o = 16; o > 0; o >>= 1) s += __shfl_down_sync(0xffffffffu, s, o);
    if (lane == 0) y[warp] = s + b[0];
}

__global__ __launch_bounds__(256) void final_softmax_k(const float* y, float* out)
{
    int s = blockIdx.x * 256 + threadIdx.x;
    if (s >= 900) return;
    float m = -3.402823466e+38f;
    for (int b = 0; b < 48; b++) m = fmaxf(m, y[b * 900 + s]);
    float sum = 0.f;
    for (int b = 0; b < 48; b++) sum += __expf(y[b * 900 + s] - m);
    float inv = 1.f / sum;
    for (int b = 0; b < 48; b++) out[b * 900 + s] = __expf(y[b * 900 + s] - m) * inv;
}